// round 13
// baseline (speedup 1.0000x reference)
#include <cuda_runtime.h>
#include <cuda_bf16.h>
#include <math.h>
#include <stdint.h>

#define BB 2
#define SS 2048
#define DD 2048
#define HH 16
#define HD 128
#define MM (BB*SS)   // 4096

// ---------------- scratch (device globals; no allocation allowed) ----------
__device__ float g_q[MM * DD];
__device__ float g_k[MM * HD];
__device__ float g_v[MM * HD];
__device__ float g_att[MM * DD];

__device__ __nv_bfloat16 g_xhi[MM * DD], g_xlo[MM * DD];
__device__ __nv_bfloat16 g_wqhi[DD * DD], g_wqlo[DD * DD];
__device__ __nv_bfloat16 g_wkhi[HD * DD], g_wklo[HD * DD];
__device__ __nv_bfloat16 g_wvhi[HD * DD], g_wvlo[HD * DD];
__device__ __nv_bfloat16 g_wohi[DD * DD], g_wolo[DD * DD];
__device__ __nv_bfloat16 g_ahi[MM * DD], g_alo[MM * DD];

// ---------------- helpers ---------------------------------------------------
__device__ __forceinline__ uint32_t smem_u32(const void* p) {
    uint32_t a;
    asm("{ .reg .u64 t; cvta.to.shared.u64 t, %1; cvt.u32.u64 %0, t; }" : "=r"(a) : "l"(p));
    return a;
}

__device__ __forceinline__ void ldmatrix_x4(uint32_t* r, uint32_t addr) {
    asm volatile("ldmatrix.sync.aligned.m8n8.x4.shared.b16 {%0,%1,%2,%3}, [%4];"
                 : "=r"(r[0]), "=r"(r[1]), "=r"(r[2]), "=r"(r[3]) : "r"(addr));
}

__device__ __forceinline__ void mma_bf16(float* c, const uint32_t* a, uint32_t b0, uint32_t b1) {
    asm volatile(
        "mma.sync.aligned.m16n8k16.row.col.f32.bf16.bf16.f32 "
        "{%0,%1,%2,%3}, {%4,%5,%6,%7}, {%8,%9}, {%0,%1,%2,%3};"
        : "+f"(c[0]), "+f"(c[1]), "+f"(c[2]), "+f"(c[3])
        : "r"(a[0]), "r"(a[1]), "r"(a[2]), "r"(a[3]), "r"(b0), "r"(b1));
}

// ---------------------------------------------------------------------------
// Split fp32 -> bf16 (hi, lo)
// ---------------------------------------------------------------------------
__global__ void split_kernel(const float* __restrict__ src,
                             __nv_bfloat16* __restrict__ hi,
                             __nv_bfloat16* __restrict__ lo, int n) {
    int i = blockIdx.x * blockDim.x + threadIdx.x;
    if (i >= n) return;
    float x = src[i];
    __nv_bfloat16 h = __float2bfloat16(x);
    hi[i] = h;
    lo[i] = __float2bfloat16(x - __bfloat162float(h));
}

// ---------------------------------------------------------------------------
// mma.sync GEMM: C[M,Ncols] = A[M,K] @ W[Ncols,K]^T, bf16 hi/lo pairs
// (3 products: hi*hi + hi*lo + lo*hi).
// Block tile 128x128, BK=32, 256 threads = 8 warps (2 m x 4 n), warp 64x32.
// Smem row r (128B) = [hi k0..31 | lo k0..31], SW128 xor-swizzled so all
// ldmatrix loads are conflict-free. Double-buffered cp.async.
// ---------------------------------------------------------------------------
#define STAGE_BYTES 32768          // A tile 16KB + W tile 16KB
#define GEMM_DYN_SMEM (2 * STAGE_BYTES + 1024)

__device__ __forceinline__ void load_stage(const __nv_bfloat16* __restrict__ Ahi,
                                           const __nv_bfloat16* __restrict__ Alo,
                                           const __nv_bfloat16* __restrict__ Whi,
                                           const __nv_bfloat16* __restrict__ Wlo,
                                           int m0, int n0, int Kdim, int k0, uint32_t sb) {
#pragma unroll
    for (int it = 0; it < 8; ++it) {
        int id = threadIdx.x + it * 256;          // 0..2047
        int tile = id >> 10;                       // 0 = A, 1 = W
        int off = (id & 1023) * 16;                // byte offset inside 16KB tile
        int row = off >> 7;                        // 128B rows
        int chunk = (off >> 4) & 7;                // 16B chunk in row
        int grow = (tile ? n0 : m0) + row;
        int kcol = k0 + (chunk & 3) * 8;
        const __nv_bfloat16* src;
        if (tile == 0) src = (chunk < 4 ? Ahi : Alo) + (size_t)grow * Kdim + kcol;
        else           src = (chunk < 4 ? Whi : Wlo) + (size_t)grow * Kdim + kcol;
        uint32_t sa = sb + (uint32_t)tile * 16384u + ((uint32_t)off ^ (((uint32_t)off >> 3) & 0x70));
        uint64_t ga = (uint64_t)__cvta_generic_to_global((const void*)src);
        asm volatile("cp.async.cg.shared.global [%0], [%1], 16;" :: "r"(sa), "l"(ga) : "memory");
    }
}

__global__ void __launch_bounds__(256, 1)
gemm_bf16pair(const __nv_bfloat16* __restrict__ Ahi, const __nv_bfloat16* __restrict__ Alo,
              const __nv_bfloat16* __restrict__ Whi, const __nv_bfloat16* __restrict__ Wlo,
              float* __restrict__ C, int Ncols, int Kdim) {
    extern __shared__ char dsm[];
    const uint32_t sbase = (smem_u32(dsm) + 1023u) & ~1023u;

    const int tid = threadIdx.x;
    const int wid = tid >> 5;
    const int lane = tid & 31;
    const int warp_m = wid >> 2;     // 0..1
    const int warp_n = wid & 3;      // 0..3
    const int m0 = blockIdx.y * 128;
    const int n0 = blockIdx.x * 128;

    float acc[4][4][4];
#pragma unroll
    for (int i = 0; i < 4; ++i)
#pragma unroll
        for (int j = 0; j < 4; ++j)
#pragma unroll
            for (int r = 0; r < 4; ++r) acc[i][j][r] = 0.f;

    const int a_row_l = (lane & 15);
    const int a_chk_l = (lane >> 4);           // 0..1
    const int b_row_l = ((lane >> 4) & 1) * 8 + (lane & 7);
    const int b_chk_l = ((lane >> 3) & 1);

    const int NC = Kdim >> 5;   // BK = 32

    load_stage(Ahi, Alo, Whi, Wlo, m0, n0, Kdim, 0, sbase);
    asm volatile("cp.async.commit_group;" ::: "memory");

    for (int c = 0; c < NC; ++c) {
        if (c + 1 < NC) {
            load_stage(Ahi, Alo, Whi, Wlo, m0, n0, Kdim, (c + 1) << 5,
                       sbase + (uint32_t)((c + 1) & 1) * STAGE_BYTES);
            asm volatile("cp.async.commit_group;" ::: "memory");
            asm volatile("cp.async.wait_group 1;" ::: "memory");
        } else {
            asm volatile("cp.async.wait_group 0;" ::: "memory");
        }
        __syncthreads();

        const uint32_t Asw = sbase + (uint32_t)(c & 1) * STAGE_BYTES;
        const uint32_t Wsw = Asw + 16384u;

#pragma unroll
        for (int ks = 0; ks < 2; ++ks) {
            uint32_t afr[2][4][4];
#pragma unroll
            for (int p = 0; p < 2; ++p)
#pragma unroll
                for (int tm = 0; tm < 4; ++tm) {
                    int row = warp_m * 64 + tm * 16 + a_row_l;
                    int chunk = p * 4 + 2 * ks + a_chk_l;
                    uint32_t byte = (uint32_t)(row * 128 + chunk * 16);
                    byte ^= ((byte >> 3) & 0x70);
                    ldmatrix_x4(afr[p][tm], Asw + byte);
                }
            uint32_t bfr[2][2][4];
#pragma unroll
            for (int p = 0; p < 2; ++p)
#pragma unroll
                for (int nb = 0; nb < 2; ++nb) {
                    int row = warp_n * 32 + nb * 16 + b_row_l;
                    int chunk = p * 4 + 2 * ks + b_chk_l;
                    uint32_t byte = (uint32_t)(row * 128 + chunk * 16);
                    byte ^= ((byte >> 3) & 0x70);
                    ldmatrix_x4(bfr[p][nb], Wsw + byte);
                }
#pragma unroll
            for (int tm = 0; tm < 4; ++tm)
#pragma unroll
                for (int nt = 0; nt < 4; ++nt) {
                    const int nb = nt >> 1, half = (nt & 1) * 2;
                    uint32_t bh0 = bfr[0][nb][half], bh1 = bfr[0][nb][half + 1];
                    uint32_t bl0 = bfr[1][nb][half], bl1 = bfr[1][nb][half + 1];
                    mma_bf16(acc[tm][nt], afr[0][tm], bh0, bh1);  // hi*hi
                    mma_bf16(acc[tm][nt], afr[0][tm], bl0, bl1);  // hi*lo
                    mma_bf16(acc[tm][nt], afr[1][tm], bh0, bh1);  // lo*hi
                }
        }
        __syncthreads();
    }

    // epilogue
    const int g = lane >> 2, tig = lane & 3;
#pragma unroll
    for (int tm = 0; tm < 4; ++tm) {
#pragma unroll
        for (int nt = 0; nt < 4; ++nt) {
            int gr = m0 + warp_m * 64 + tm * 16 + g;
            int gc = n0 + warp_n * 32 + nt * 8 + tig * 2;
            *(float2*)&C[(size_t)gr * Ncols + gc] = make_float2(acc[tm][nt][0], acc[tm][nt][1]);
            *(float2*)&C[(size_t)(gr + 8) * Ncols + gc] = make_float2(acc[tm][nt][2], acc[tm][nt][3]);
        }
    }
}

// ---------------------------------------------------------------------------
// In-place RoPE
// ---------------------------------------------------------------------------
__global__ void rope_kernel(float* __restrict__ tns,
                            const float* __restrict__ cosT,
                            const float* __restrict__ sinT,
                            int rowsize, int npairs) {
    int p = blockIdx.x * blockDim.x + threadIdx.x;
    if (p >= npairs) return;
    const int hp = rowsize >> 1;
    const int row = p / hp;
    const int pc = p - row * hp;
    const int s = row & (SS - 1);
    const int i = pc & 63;
    const float c = cosT[s * 64 + i];
    const float sn = sinT[s * 64 + i];
    float* base = tns + (size_t)row * rowsize + 2 * pc;
    const float x0 = base[0], x1 = base[1];
    base[0] = x0 * c - x1 * sn;
    base[1] = x0 * sn + x1 * c;
}

// ---------------------------------------------------------------------------
// Causal MQA flash attention, fp32. Thread `sub` owns contiguous dims
// [32*sub, 32*sub+32) so all shared reads are conflict-free LDS.128.
// ---------------------------------------------------------------------------
__global__ void __launch_bounds__(128) flash_kernel(const float* __restrict__ q,
                                                    const float* __restrict__ k,
                                                    const float* __restrict__ v,
                                                    float* __restrict__ out) {
    const int qb = blockIdx.x;
    const int h = blockIdx.y;
    const int b = blockIdx.z;
    const int row = threadIdx.x >> 2;
    const int sub = threadIdx.x & 3;
    const int qi = qb * 32 + row;

    __shared__ float Ks[32][HD];
    __shared__ float Vs[32][HD];

    float qf[32], o[32];
    const float* qrow = q + ((size_t)b * SS + qi) * DD + h * HD + sub * 32;
#pragma unroll
    for (int t4 = 0; t4 < 8; ++t4) {
        float4 v4 = *(const float4*)(qrow + 4 * t4);
        qf[4 * t4 + 0] = v4.x; qf[4 * t4 + 1] = v4.y;
        qf[4 * t4 + 2] = v4.z; qf[4 * t4 + 3] = v4.w;
    }
#pragma unroll
    for (int t = 0; t < 32; ++t) o[t] = 0.f;

    float m = -1e30f, l = 0.f;
    const float scale = 0.08838834764831845f;

    const int kend = qb * 32 + 32;
    for (int k0 = 0; k0 < kend; k0 += 32) {
        {
            const float4* kg = (const float4*)(k + ((size_t)b * SS + k0) * HD);
            const float4* vg = (const float4*)(v + ((size_t)b * SS + k0) * HD);
            float4* ks4 = (float4*)&Ks[0][0];
            float4* vs4 = (float4*)&Vs[0][0];
#pragma unroll
            for (int it = 0; it < 8; ++it) {
                int idx = threadIdx.x + it * 128;
                ks4[idx] = kg[idx];
                vs4[idx] = vg[idx];
            }
        }
        __syncthreads();

        float s[32];
#pragma unroll
        for (int kk = 0; kk < 32; ++kk) {
            const float4* kp = (const float4*)&Ks[kk][sub * 32];
            float acc = 0.f;
#pragma unroll
            for (int t4 = 0; t4 < 8; ++t4) {
                float4 kv = kp[t4];
                acc += qf[4 * t4 + 0] * kv.x + qf[4 * t4 + 1] * kv.y +
                       qf[4 * t4 + 2] * kv.z + qf[4 * t4 + 3] * kv.w;
            }
            s[kk] = acc;
        }
#pragma unroll
        for (int kk = 0; kk < 32; ++kk) {
            float t0 = s[kk];
            t0 += __shfl_xor_sync(0xffffffffu, t0, 1);
            t0 += __shfl_xor_sync(0xffffffffu, t0, 2);
            t0 *= scale;
            if (k0 + kk > qi) t0 = -1e30f;
            s[kk] = t0;
        }
        float tilem = -1e30f;
#pragma unroll
        for (int kk = 0; kk < 32; ++kk) tilem = fmaxf(tilem, s[kk]);
        const float mnew = fmaxf(m, tilem);
        const float corr = __expf(m - mnew);
        float ladd = 0.f;
#pragma unroll
        for (int kk = 0; kk < 32; ++kk) {
            s[kk] = __expf(s[kk] - mnew);
            ladd += s[kk];
        }
        l = l * corr + ladd;
        m = mnew;
#pragma unroll
        for (int t = 0; t < 32; ++t) o[t] *= corr;
#pragma unroll
        for (int kk = 0; kk < 32; ++kk) {
            const float p = s[kk];
            const float4* vp = (const float4*)&Vs[kk][sub * 32];
#pragma unroll
            for (int t4 = 0; t4 < 8; ++t4) {
                float4 vv = vp[t4];
                o[4 * t4 + 0] += p * vv.x; o[4 * t4 + 1] += p * vv.y;
                o[4 * t4 + 2] += p * vv.z; o[4 * t4 + 3] += p * vv.w;
            }
        }
        __syncthreads();
    }

    const float inv = 1.f / l;
    float* orow = out + ((size_t)b * SS + qi) * DD + h * HD + sub * 32;
#pragma unroll
    for (int t4 = 0; t4 < 8; ++t4) {
        float4 v4 = make_float4(o[4 * t4 + 0] * inv, o[4 * t4 + 1] * inv,
                                o[4 * t4 + 2] * inv, o[4 * t4 + 3] * inv);
        *(float4*)(orow + 4 * t4) = v4;
    }
}

// ---------------------------------------------------------------------------
extern "C" void kernel_launch(void* const* d_in, const int* in_sizes, int n_in,
                              void* d_out, int out_size) {
    const float* x    = (const float*)d_in[0];
    const float* Wq   = (const float*)d_in[1];
    const float* Wk   = (const float*)d_in[2];
    const float* Wv   = (const float*)d_in[3];
    const float* Wo   = (const float*)d_in[4];
    const float* rcos = (const float*)d_in[5];
    const float* rsin = (const float*)d_in[6];
    float* out = (float*)d_out;

    float *q_p, *k_p, *v_p, *att_p;
    cudaGetSymbolAddress((void**)&q_p, g_q);
    cudaGetSymbolAddress((void**)&k_p, g_k);
    cudaGetSymbolAddress((void**)&v_p, g_v);
    cudaGetSymbolAddress((void**)&att_p, g_att);

    __nv_bfloat16 *xhi, *xlo, *wqhi, *wqlo, *wkhi, *wklo, *wvhi, *wvlo, *wohi, *wolo, *ahi, *alo;
    cudaGetSymbolAddress((void**)&xhi, g_xhi);   cudaGetSymbolAddress((void**)&xlo, g_xlo);
    cudaGetSymbolAddress((void**)&wqhi, g_wqhi); cudaGetSymbolAddress((void**)&wqlo, g_wqlo);
    cudaGetSymbolAddress((void**)&wkhi, g_wkhi); cudaGetSymbolAddress((void**)&wklo, g_wklo);
    cudaGetSymbolAddress((void**)&wvhi, g_wvhi); cudaGetSymbolAddress((void**)&wvlo, g_wvlo);
    cudaGetSymbolAddress((void**)&wohi, g_wohi); cudaGetSymbolAddress((void**)&wolo, g_wolo);
    cudaGetSymbolAddress((void**)&ahi, g_ahi);   cudaGetSymbolAddress((void**)&alo, g_alo);

    cudaFuncSetAttribute(gemm_bf16pair, cudaFuncAttributeMaxDynamicSharedMemorySize, GEMM_DYN_SMEM);

    const int M = MM;  // 4096

    // splits
    split_kernel<<<(M * DD + 255) / 256, 256>>>(x, xhi, xlo, M * DD);
    split_kernel<<<(DD * DD + 255) / 256, 256>>>(Wq, wqhi, wqlo, DD * DD);
    split_kernel<<<(HD * DD + 255) / 256, 256>>>(Wk, wkhi, wklo, HD * DD);
    split_kernel<<<(HD * DD + 255) / 256, 256>>>(Wv, wvhi, wvlo, HD * DD);
    split_kernel<<<(DD * DD + 255) / 256, 256>>>(Wo, wohi, wolo, DD * DD);

    // projections on tensor cores (mma.sync)
    gemm_bf16pair<<<dim3(DD / 128, M / 128), 256, GEMM_DYN_SMEM>>>(xhi, xlo, wqhi, wqlo, q_p, DD, DD);
    gemm_bf16pair<<<dim3(HD / 128, M / 128), 256, GEMM_DYN_SMEM>>>(xhi, xlo, wkhi, wklo, k_p, HD, DD);
    gemm_bf16pair<<<dim3(HD / 128, M / 128), 256, GEMM_DYN_SMEM>>>(xhi, xlo, wvhi, wvlo, v_p, HD, DD);

    // RoPE
    {
        int npq = M * DD / 2;
        rope_kernel<<<(npq + 255) / 256, 256>>>(q_p, rcos, rsin, DD, npq);
        int npk = M * HD / 2;
        rope_kernel<<<(npk + 255) / 256, 256>>>(k_p, rcos, rsin, HD, npk);
    }

    // attention
    flash_kernel<<<dim3(SS / 32, HH, BB), 128>>>(q_p, k_p, v_p, att_p);

    // output projection
    split_kernel<<<(M * DD + 255) / 256, 256>>>(att_p, ahi, alo, M * DD);
    gemm_bf16pair<<<dim3(DD / 128, M / 128), 256, GEMM_DYN_SMEM>>>(ahi, alo, wohi, wolo, out, DD, DD);
}

// round 14
// speedup vs baseline: 2.5600x; 2.5600x over previous
#include <cuda_runtime.h>
#include <cuda_bf16.h>
#include <math.h>
#include <stdint.h>

#define BB 2
#define SS 2048
#define DD 2048
#define HH 16
#define HD 128
#define MM (BB*SS)   // 4096

// ---------------- scratch (device globals; no allocation allowed) ----------
__device__ float g_q[MM * DD];
__device__ float g_k[MM * HD];
__device__ float g_v[MM * HD];
__device__ float g_att[MM * DD];

__device__ __nv_bfloat16 g_xhi[MM * DD], g_xlo[MM * DD];
__device__ __nv_bfloat16 g_wqhi[DD * DD], g_wqlo[DD * DD];
__device__ __nv_bfloat16 g_wkhi[HD * DD], g_wklo[HD * DD];
__device__ __nv_bfloat16 g_wvhi[HD * DD], g_wvlo[HD * DD];
__device__ __nv_bfloat16 g_wohi[DD * DD], g_wolo[DD * DD];
__device__ __nv_bfloat16 g_ahi[MM * DD], g_alo[MM * DD];

// ---------------- helpers ---------------------------------------------------
__device__ __forceinline__ uint32_t smem_u32(const void* p) {
    uint32_t a;
    asm("{ .reg .u64 t; cvta.to.shared.u64 t, %1; cvt.u32.u64 %0, t; }" : "=r"(a) : "l"(p));
    return a;
}

__device__ __forceinline__ void ldmatrix_x4(uint32_t* r, uint32_t addr) {
    asm volatile("ldmatrix.sync.aligned.m8n8.x4.shared.b16 {%0,%1,%2,%3}, [%4];"
                 : "=r"(r[0]), "=r"(r[1]), "=r"(r[2]), "=r"(r[3]) : "r"(addr));
}

__device__ __forceinline__ void mma_bf16(float* c, const uint32_t* a, uint32_t b0, uint32_t b1) {
    asm volatile(
        "mma.sync.aligned.m16n8k16.row.col.f32.bf16.bf16.f32 "
        "{%0,%1,%2,%3}, {%4,%5,%6,%7}, {%8,%9}, {%0,%1,%2,%3};"
        : "+f"(c[0]), "+f"(c[1]), "+f"(c[2]), "+f"(c[3])
        : "r"(a[0]), "r"(a[1]), "r"(a[2]), "r"(a[3]), "r"(b0), "r"(b1));
}

// ---------------------------------------------------------------------------
// Split fp32 -> bf16 (hi, lo)
// ---------------------------------------------------------------------------
__global__ void split_kernel(const float* __restrict__ src,
                             __nv_bfloat16* __restrict__ hi,
                             __nv_bfloat16* __restrict__ lo, int n) {
    int i = blockIdx.x * blockDim.x + threadIdx.x;
    if (i >= n) return;
    float x = src[i];
    __nv_bfloat16 h = __float2bfloat16(x);
    hi[i] = h;
    lo[i] = __float2bfloat16(x - __bfloat162float(h));
}

// ---------------------------------------------------------------------------
// mma.sync GEMM (silicon-validated numerics, rel_err 2.2e-5).
// 3 MMA passes (hi*hi, hi*lo, lo*hi) issued as separate sweeps so same-
// accumulator MMAs have dependency distance 16 instead of back-to-back.
// ---------------------------------------------------------------------------
#define STAGE_BYTES 32768          // A tile 16KB + W tile 16KB
#define GEMM_DYN_SMEM (2 * STAGE_BYTES + 1024)

__device__ __forceinline__ void load_stage(const __nv_bfloat16* __restrict__ Ahi,
                                           const __nv_bfloat16* __restrict__ Alo,
                                           const __nv_bfloat16* __restrict__ Whi,
                                           const __nv_bfloat16* __restrict__ Wlo,
                                           int m0, int n0, int Kdim, int k0, uint32_t sb) {
#pragma unroll
    for (int it = 0; it < 8; ++it) {
        int id = threadIdx.x + it * 256;          // 0..2047
        int tile = id >> 10;                       // 0 = A, 1 = W
        int off = (id & 1023) * 16;                // byte offset inside 16KB tile
        int row = off >> 7;                        // 128B rows
        int chunk = (off >> 4) & 7;                // 16B chunk in row
        int grow = (tile ? n0 : m0) + row;
        int kcol = k0 + (chunk & 3) * 8;
        const __nv_bfloat16* src;
        if (tile == 0) src = (chunk < 4 ? Ahi : Alo) + (size_t)grow * Kdim + kcol;
        else           src = (chunk < 4 ? Whi : Wlo) + (size_t)grow * Kdim + kcol;
        uint32_t sa = sb + (uint32_t)tile * 16384u + ((uint32_t)off ^ (((uint32_t)off >> 3) & 0x70));
        uint64_t ga = (uint64_t)__cvta_generic_to_global((const void*)src);
        asm volatile("cp.async.cg.shared.global [%0], [%1], 16;" :: "r"(sa), "l"(ga) : "memory");
    }
}

__global__ void __launch_bounds__(256, 1)
gemm_bf16pair(const __nv_bfloat16* __restrict__ Ahi, const __nv_bfloat16* __restrict__ Alo,
              const __nv_bfloat16* __restrict__ Whi, const __nv_bfloat16* __restrict__ Wlo,
              float* __restrict__ C, int Ncols, int Kdim) {
    extern __shared__ char dsm[];
    const uint32_t sbase = (smem_u32(dsm) + 1023u) & ~1023u;

    const int tid = threadIdx.x;
    const int wid = tid >> 5;
    const int lane = tid & 31;
    const int warp_m = wid >> 2;     // 0..1
    const int warp_n = wid & 3;      // 0..3
    const int m0 = blockIdx.y * 128;
    const int n0 = blockIdx.x * 128;

    float acc[4][4][4];
#pragma unroll
    for (int i = 0; i < 4; ++i)
#pragma unroll
        for (int j = 0; j < 4; ++j)
#pragma unroll
            for (int r = 0; r < 4; ++r) acc[i][j][r] = 0.f;

    const int a_row_l = (lane & 15);
    const int a_chk_l = (lane >> 4);           // 0..1
    const int b_row_l = ((lane >> 4) & 1) * 8 + (lane & 7);
    const int b_chk_l = ((lane >> 3) & 1);

    const int NC = Kdim >> 5;   // BK = 32

    load_stage(Ahi, Alo, Whi, Wlo, m0, n0, Kdim, 0, sbase);
    asm volatile("cp.async.commit_group;" ::: "memory");

    for (int c = 0; c < NC; ++c) {
        if (c + 1 < NC) {
            load_stage(Ahi, Alo, Whi, Wlo, m0, n0, Kdim, (c + 1) << 5,
                       sbase + (uint32_t)((c + 1) & 1) * STAGE_BYTES);
            asm volatile("cp.async.commit_group;" ::: "memory");
            asm volatile("cp.async.wait_group 1;" ::: "memory");
        } else {
            asm volatile("cp.async.wait_group 0;" ::: "memory");
        }
        __syncthreads();

        const uint32_t Asw = sbase + (uint32_t)(c & 1) * STAGE_BYTES;
        const uint32_t Wsw = Asw + 16384u;

#pragma unroll
        for (int ks = 0; ks < 2; ++ks) {
            uint32_t afr[2][4][4];
#pragma unroll
            for (int p = 0; p < 2; ++p)
#pragma unroll
                for (int tm = 0; tm < 4; ++tm) {
                    int row = warp_m * 64 + tm * 16 + a_row_l;
                    int chunk = p * 4 + 2 * ks + a_chk_l;
                    uint32_t byte = (uint32_t)(row * 128 + chunk * 16);
                    byte ^= ((byte >> 3) & 0x70);
                    ldmatrix_x4(afr[p][tm], Asw + byte);
                }
            uint32_t bfr[2][2][4];
#pragma unroll
            for (int p = 0; p < 2; ++p)
#pragma unroll
                for (int nb = 0; nb < 2; ++nb) {
                    int row = warp_n * 32 + nb * 16 + b_row_l;
                    int chunk = p * 4 + 2 * ks + b_chk_l;
                    uint32_t byte = (uint32_t)(row * 128 + chunk * 16);
                    byte ^= ((byte >> 3) & 0x70);
                    ldmatrix_x4(bfr[p][nb], Wsw + byte);
                }
            // Pass 1: hi*hi  (16 independent MMAs)
#pragma unroll
            for (int tm = 0; tm < 4; ++tm)
#pragma unroll
                for (int nt = 0; nt < 4; ++nt) {
                    const int nb = nt >> 1, half = (nt & 1) * 2;
                    mma_bf16(acc[tm][nt], afr[0][tm], bfr[0][nb][half], bfr[0][nb][half + 1]);
                }
            // Pass 2: hi*lo
#pragma unroll
            for (int tm = 0; tm < 4; ++tm)
#pragma unroll
                for (int nt = 0; nt < 4; ++nt) {
                    const int nb = nt >> 1, half = (nt & 1) * 2;
                    mma_bf16(acc[tm][nt], afr[0][tm], bfr[1][nb][half], bfr[1][nb][half + 1]);
                }
            // Pass 3: lo*hi
#pragma unroll
            for (int tm = 0; tm < 4; ++tm)
#pragma unroll
                for (int nt = 0; nt < 4; ++nt) {
                    const int nb = nt >> 1, half = (nt & 1) * 2;
                    mma_bf16(acc[tm][nt], afr[1][tm], bfr[0][nb][half], bfr[0][nb][half + 1]);
                }
        }
        __syncthreads();
    }

    // epilogue
    const int g = lane >> 2, tig = lane & 3;
#pragma unroll
    for (int tm = 0; tm < 4; ++tm) {
#pragma unroll
        for (int nt = 0; nt < 4; ++nt) {
            int gr = m0 + warp_m * 64 + tm * 16 + g;
            int gc = n0 + warp_n * 32 + nt * 8 + tig * 2;
            *(float2*)&C[(size_t)gr * Ncols + gc] = make_float2(acc[tm][nt][0], acc[tm][nt][1]);
            *(float2*)&C[(size_t)(gr + 8) * Ncols + gc] = make_float2(acc[tm][nt][2], acc[tm][nt][3]);
        }
    }
}

// ---------------------------------------------------------------------------
// In-place RoPE
// ---------------------------------------------------------------------------
__global__ void rope_kernel(float* __restrict__ tns,
                            const float* __restrict__ cosT,
                            const float* __restrict__ sinT,
                            int rowsize, int npairs) {
    int p = blockIdx.x * blockDim.x + threadIdx.x;
    if (p >= npairs) return;
    const int hp = rowsize >> 1;
    const int row = p / hp;
    const int pc = p - row * hp;
    const int s = row & (SS - 1);
    const int i = pc & 63;
    const float c = cosT[s * 64 + i];
    const float sn = sinT[s * 64 + i];
    float* base = tns + (size_t)row * rowsize + 2 * pc;
    const float x0 = base[0], x1 = base[1];
    base[0] = x0 * c - x1 * sn;
    base[1] = x0 * sn + x1 * c;
}

// ---------------------------------------------------------------------------
// Causal MQA flash attention — EXACT R0 version (component of the measured
// 5162us config): interleaved dim ownership, conflict-free scalar LDS.
// ---------------------------------------------------------------------------
__global__ void flash_kernel(const float* __restrict__ q,
                             const float* __restrict__ k,
                             const float* __restrict__ v,
                             float* __restrict__ out) {
    const int qb  = blockIdx.x;
    const int h   = blockIdx.y;
    const int b   = blockIdx.z;
    const int row = threadIdx.x >> 2;   // 0..31
    const int sub = threadIdx.x & 3;
    const int qi  = qb * 32 + row;

    __shared__ float Ks[32][HD];
    __shared__ float Vs[32][HD];

    float qf[32];
    const float* qrow = q + ((size_t)b * SS + qi) * DD + h * HD;
#pragma unroll
    for (int tt = 0; tt < 32; ++tt) qf[tt] = qrow[sub + 4 * tt];

    float o[32];
#pragma unroll
    for (int tt = 0; tt < 32; ++tt) o[tt] = 0.f;

    float m = -1e30f, l = 0.f;
    const float scale = 0.08838834764831845f;  // 1/sqrt(128)

    const int kend = qb * 32 + 32;  // exclusive
    for (int k0 = 0; k0 < kend; k0 += 32) {
        {
            const float4* kg = (const float4*)(k + ((size_t)b * SS + k0) * HD);
            const float4* vg = (const float4*)(v + ((size_t)b * SS + k0) * HD);
            float4* ks4 = (float4*)&Ks[0][0];
            float4* vs4 = (float4*)&Vs[0][0];
#pragma unroll
            for (int it = 0; it < 8; ++it) {
                int idx = threadIdx.x + it * 128;
                ks4[idx] = kg[idx];
                vs4[idx] = vg[idx];
            }
        }
        __syncthreads();

        float s[32];
#pragma unroll
        for (int kk = 0; kk < 32; ++kk) {
            float acc = 0.f;
#pragma unroll
            for (int tt = 0; tt < 32; ++tt) acc += qf[tt] * Ks[kk][sub + 4 * tt];
            s[kk] = acc;
        }
#pragma unroll
        for (int kk = 0; kk < 32; ++kk) {
            float t0 = s[kk];
            t0 += __shfl_xor_sync(0xffffffffu, t0, 1);
            t0 += __shfl_xor_sync(0xffffffffu, t0, 2);
            t0 *= scale;
            if (k0 + kk > qi) t0 = -1e30f;
            s[kk] = t0;
        }
        float tilem = -1e30f;
#pragma unroll
        for (int kk = 0; kk < 32; ++kk) tilem = fmaxf(tilem, s[kk]);
        const float mnew = fmaxf(m, tilem);
        const float corr = __expf(m - mnew);
        float ladd = 0.f;
#pragma unroll
        for (int kk = 0; kk < 32; ++kk) {
            s[kk] = __expf(s[kk] - mnew);
            ladd += s[kk];
        }
        l = l * corr + ladd;
        m = mnew;
#pragma unroll
        for (int tt = 0; tt < 32; ++tt) o[tt] *= corr;
#pragma unroll
        for (int kk = 0; kk < 32; ++kk) {
            const float p = s[kk];
#pragma unroll
            for (int tt = 0; tt < 32; ++tt) o[tt] += p * Vs[kk][sub + 4 * tt];
        }
        __syncthreads();
    }

    const float inv = 1.f / l;
    float* orow = out + ((size_t)b * SS + qi) * DD + h * HD;
#pragma unroll
    for (int tt = 0; tt < 32; ++tt) orow[sub + 4 * tt] = o[tt] * inv;
}

// ---------------------------------------------------------------------------
extern "C" void kernel_launch(void* const* d_in, const int* in_sizes, int n_in,
                              void* d_out, int out_size) {
    const float* x    = (const float*)d_in[0];
    const float* Wq   = (const float*)d_in[1];
    const float* Wk   = (const float*)d_in[2];
    const float* Wv   = (const float*)d_in[3];
    const float* Wo   = (const float*)d_in[4];
    const float* rcos = (const float*)d_in[5];
    const float* rsin = (const float*)d_in[6];
    float* out = (float*)d_out;

    float *q_p, *k_p, *v_p, *att_p;
    cudaGetSymbolAddress((void**)&q_p, g_q);
    cudaGetSymbolAddress((void**)&k_p, g_k);
    cudaGetSymbolAddress((void**)&v_p, g_v);
    cudaGetSymbolAddress((void**)&att_p, g_att);

    __nv_bfloat16 *xhi, *xlo, *wqhi, *wqlo, *wkhi, *wklo, *wvhi, *wvlo, *wohi, *wolo, *ahi, *alo;
    cudaGetSymbolAddress((void**)&xhi, g_xhi);   cudaGetSymbolAddress((void**)&xlo, g_xlo);
    cudaGetSymbolAddress((void**)&wqhi, g_wqhi); cudaGetSymbolAddress((void**)&wqlo, g_wqlo);
    cudaGetSymbolAddress((void**)&wkhi, g_wkhi); cudaGetSymbolAddress((void**)&wklo, g_wklo);
    cudaGetSymbolAddress((void**)&wvhi, g_wvhi); cudaGetSymbolAddress((void**)&wvlo, g_wvlo);
    cudaGetSymbolAddress((void**)&wohi, g_wohi); cudaGetSymbolAddress((void**)&wolo, g_wolo);
    cudaGetSymbolAddress((void**)&ahi, g_ahi);   cudaGetSymbolAddress((void**)&alo, g_alo);

    cudaFuncSetAttribute(gemm_bf16pair, cudaFuncAttributeMaxDynamicSharedMemorySize, GEMM_DYN_SMEM);

    const int M = MM;  // 4096

    // splits
    split_kernel<<<(M * DD + 255) / 256, 256>>>(x, xhi, xlo, M * DD);
    split_kernel<<<(DD * DD + 255) / 256, 256>>>(Wq, wqhi, wqlo, DD * DD);
    split_kernel<<<(HD * DD + 255) / 256, 256>>>(Wk, wkhi, wklo, HD * DD);
    split_kernel<<<(HD * DD + 255) / 256, 256>>>(Wv, wvhi, wvlo, HD * DD);
    split_kernel<<<(DD * DD + 255) / 256, 256>>>(Wo, wohi, wolo, DD * DD);

    // projections on tensor cores (mma.sync)
    gemm_bf16pair<<<dim3(DD / 128, M / 128), 256, GEMM_DYN_SMEM>>>(xhi, xlo, wqhi, wqlo, q_p, DD, DD);
    gemm_bf16pair<<<dim3(HD / 128, M / 128), 256, GEMM_DYN_SMEM>>>(xhi, xlo, wkhi, wklo, k_p, HD, DD);
    gemm_bf16pair<<<dim3(HD / 128, M / 128), 256, GEMM_DYN_SMEM>>>(xhi, xlo, wvhi, wvlo, v_p, HD, DD);

    // RoPE
    {
        int npq = M * DD / 2;
        rope_kernel<<<(npq + 255) / 256, 256>>>(q_p, rcos, rsin, DD, npq);
        int npk = M * HD / 2;
        rope_kernel<<<(npk + 255) / 256, 256>>>(k_p, rcos, rsin, HD, npk);
    }

    // attention (R0 version)
    flash_kernel<<<dim3(SS / 32, HH, BB), 128>>>(q_p, k_p, v_p, att_p);

    // output projection
    split_kernel<<<(M * DD + 255) / 256, 256>>>(att_p, ahi, alo, M * DD);
    gemm_bf16pair<<<dim3(DD / 128, M / 128), 256, GEMM_DYN_SMEM>>>(ahi, alo, wohi, wolo, out, DD, DD);
}

// round 15
// speedup vs baseline: 2.6647x; 1.0409x over previous
#include <cuda_runtime.h>
#include <cuda_bf16.h>
#include <math.h>
#include <stdint.h>

#define BB 2
#define SS 2048
#define DD 2048
#define HH 16
#define HD 128
#define MM (BB*SS)   // 4096

// ---------------- scratch (device globals; no allocation allowed) ----------
__device__ float g_q[MM * DD];
__device__ float g_k[MM * HD];
__device__ float g_v[MM * HD];
__device__ float g_att[MM * DD];

__device__ __nv_bfloat16 g_xhi[MM * DD], g_xlo[MM * DD];
__device__ __nv_bfloat16 g_wqhi[DD * DD], g_wqlo[DD * DD];
__device__ __nv_bfloat16 g_wkhi[HD * DD], g_wklo[HD * DD];
__device__ __nv_bfloat16 g_wvhi[HD * DD], g_wvlo[HD * DD];
__device__ __nv_bfloat16 g_wohi[DD * DD], g_wolo[DD * DD];
__device__ __nv_bfloat16 g_ahi[MM * DD], g_alo[MM * DD];

// ---------------- helpers ---------------------------------------------------
__device__ __forceinline__ uint32_t smem_u32(const void* p) {
    uint32_t a;
    asm("{ .reg .u64 t; cvta.to.shared.u64 t, %1; cvt.u32.u64 %0, t; }" : "=r"(a) : "l"(p));
    return a;
}

__device__ __forceinline__ void ldmatrix_x4(uint32_t* r, uint32_t addr) {
    asm volatile("ldmatrix.sync.aligned.m8n8.x4.shared.b16 {%0,%1,%2,%3}, [%4];"
                 : "=r"(r[0]), "=r"(r[1]), "=r"(r[2]), "=r"(r[3]) : "r"(addr));
}

__device__ __forceinline__ void mma_bf16(float* c, const uint32_t* a, uint32_t b0, uint32_t b1) {
    asm volatile(
        "mma.sync.aligned.m16n8k16.row.col.f32.bf16.bf16.f32 "
        "{%0,%1,%2,%3}, {%4,%5,%6,%7}, {%8,%9}, {%0,%1,%2,%3};"
        : "+f"(c[0]), "+f"(c[1]), "+f"(c[2]), "+f"(c[3])
        : "r"(a[0]), "r"(a[1]), "r"(a[2]), "r"(a[3]), "r"(b0), "r"(b1));
}

// ---------------------------------------------------------------------------
// Split fp32 -> bf16 (hi, lo)
// ---------------------------------------------------------------------------
__global__ void split_kernel(const float* __restrict__ src,
                             __nv_bfloat16* __restrict__ hi,
                             __nv_bfloat16* __restrict__ lo, int n) {
    int i = blockIdx.x * blockDim.x + threadIdx.x;
    if (i >= n) return;
    float x = src[i];
    __nv_bfloat16 h = __float2bfloat16(x);
    hi[i] = h;
    lo[i] = __float2bfloat16(x - __bfloat162float(h));
}

// ---------------------------------------------------------------------------
// mma.sync GEMM (unchanged from measured 3619us config).
// ---------------------------------------------------------------------------
#define STAGE_BYTES 32768          // A tile 16KB + W tile 16KB
#define GEMM_DYN_SMEM (2 * STAGE_BYTES + 1024)

__device__ __forceinline__ void load_stage(const __nv_bfloat16* __restrict__ Ahi,
                                           const __nv_bfloat16* __restrict__ Alo,
                                           const __nv_bfloat16* __restrict__ Whi,
                                           const __nv_bfloat16* __restrict__ Wlo,
                                           int m0, int n0, int Kdim, int k0, uint32_t sb) {
#pragma unroll
    for (int it = 0; it < 8; ++it) {
        int id = threadIdx.x + it * 256;          // 0..2047
        int tile = id >> 10;                       // 0 = A, 1 = W
        int off = (id & 1023) * 16;                // byte offset inside 16KB tile
        int row = off >> 7;                        // 128B rows
        int chunk = (off >> 4) & 7;                // 16B chunk in row
        int grow = (tile ? n0 : m0) + row;
        int kcol = k0 + (chunk & 3) * 8;
        const __nv_bfloat16* src;
        if (tile == 0) src = (chunk < 4 ? Ahi : Alo) + (size_t)grow * Kdim + kcol;
        else           src = (chunk < 4 ? Whi : Wlo) + (size_t)grow * Kdim + kcol;
        uint32_t sa = sb + (uint32_t)tile * 16384u + ((uint32_t)off ^ (((uint32_t)off >> 3) & 0x70));
        uint64_t ga = (uint64_t)__cvta_generic_to_global((const void*)src);
        asm volatile("cp.async.cg.shared.global [%0], [%1], 16;" :: "r"(sa), "l"(ga) : "memory");
    }
}

__global__ void __launch_bounds__(256, 1)
gemm_bf16pair(const __nv_bfloat16* __restrict__ Ahi, const __nv_bfloat16* __restrict__ Alo,
              const __nv_bfloat16* __restrict__ Whi, const __nv_bfloat16* __restrict__ Wlo,
              float* __restrict__ C, int Ncols, int Kdim) {
    extern __shared__ char dsm[];
    const uint32_t sbase = (smem_u32(dsm) + 1023u) & ~1023u;

    const int tid = threadIdx.x;
    const int wid = tid >> 5;
    const int lane = tid & 31;
    const int warp_m = wid >> 2;     // 0..1
    const int warp_n = wid & 3;      // 0..3
    const int m0 = blockIdx.y * 128;
    const int n0 = blockIdx.x * 128;

    float acc[4][4][4];
#pragma unroll
    for (int i = 0; i < 4; ++i)
#pragma unroll
        for (int j = 0; j < 4; ++j)
#pragma unroll
            for (int r = 0; r < 4; ++r) acc[i][j][r] = 0.f;

    const int a_row_l = (lane & 15);
    const int a_chk_l = (lane >> 4);           // 0..1
    const int b_row_l = ((lane >> 4) & 1) * 8 + (lane & 7);
    const int b_chk_l = ((lane >> 3) & 1);

    const int NC = Kdim >> 5;   // BK = 32

    load_stage(Ahi, Alo, Whi, Wlo, m0, n0, Kdim, 0, sbase);
    asm volatile("cp.async.commit_group;" ::: "memory");

    for (int c = 0; c < NC; ++c) {
        if (c + 1 < NC) {
            load_stage(Ahi, Alo, Whi, Wlo, m0, n0, Kdim, (c + 1) << 5,
                       sbase + (uint32_t)((c + 1) & 1) * STAGE_BYTES);
            asm volatile("cp.async.commit_group;" ::: "memory");
            asm volatile("cp.async.wait_group 1;" ::: "memory");
        } else {
            asm volatile("cp.async.wait_group 0;" ::: "memory");
        }
        __syncthreads();

        const uint32_t Asw = sbase + (uint32_t)(c & 1) * STAGE_BYTES;
        const uint32_t Wsw = Asw + 16384u;

#pragma unroll
        for (int ks = 0; ks < 2; ++ks) {
            uint32_t afr[2][4][4];
#pragma unroll
            for (int p = 0; p < 2; ++p)
#pragma unroll
                for (int tm = 0; tm < 4; ++tm) {
                    int row = warp_m * 64 + tm * 16 + a_row_l;
                    int chunk = p * 4 + 2 * ks + a_chk_l;
                    uint32_t byte = (uint32_t)(row * 128 + chunk * 16);
                    byte ^= ((byte >> 3) & 0x70);
                    ldmatrix_x4(afr[p][tm], Asw + byte);
                }
            uint32_t bfr[2][2][4];
#pragma unroll
            for (int p = 0; p < 2; ++p)
#pragma unroll
                for (int nb = 0; nb < 2; ++nb) {
                    int row = warp_n * 32 + nb * 16 + b_row_l;
                    int chunk = p * 4 + 2 * ks + b_chk_l;
                    uint32_t byte = (uint32_t)(row * 128 + chunk * 16);
                    byte ^= ((byte >> 3) & 0x70);
                    ldmatrix_x4(bfr[p][nb], Wsw + byte);
                }
            // Pass 1: hi*hi
#pragma unroll
            for (int tm = 0; tm < 4; ++tm)
#pragma unroll
                for (int nt = 0; nt < 4; ++nt) {
                    const int nb = nt >> 1, half = (nt & 1) * 2;
                    mma_bf16(acc[tm][nt], afr[0][tm], bfr[0][nb][half], bfr[0][nb][half + 1]);
                }
            // Pass 2: hi*lo
#pragma unroll
            for (int tm = 0; tm < 4; ++tm)
#pragma unroll
                for (int nt = 0; nt < 4; ++nt) {
                    const int nb = nt >> 1, half = (nt & 1) * 2;
                    mma_bf16(acc[tm][nt], afr[0][tm], bfr[1][nb][half], bfr[1][nb][half + 1]);
                }
            // Pass 3: lo*hi
#pragma unroll
            for (int tm = 0; tm < 4; ++tm)
#pragma unroll
                for (int nt = 0; nt < 4; ++nt) {
                    const int nb = nt >> 1, half = (nt & 1) * 2;
                    mma_bf16(acc[tm][nt], afr[1][tm], bfr[0][nb][half], bfr[0][nb][half + 1]);
                }
        }
        __syncthreads();
    }

    // epilogue
    const int g = lane >> 2, tig = lane & 3;
#pragma unroll
    for (int tm = 0; tm < 4; ++tm) {
#pragma unroll
        for (int nt = 0; nt < 4; ++nt) {
            int gr = m0 + warp_m * 64 + tm * 16 + g;
            int gc = n0 + warp_n * 32 + nt * 8 + tig * 2;
            *(float2*)&C[(size_t)gr * Ncols + gc] = make_float2(acc[tm][nt][0], acc[tm][nt][1]);
            *(float2*)&C[(size_t)(gr + 8) * Ncols + gc] = make_float2(acc[tm][nt][2], acc[tm][nt][3]);
        }
    }
}

// ---------------------------------------------------------------------------
// In-place RoPE
// ---------------------------------------------------------------------------
__global__ void rope_kernel(float* __restrict__ tns,
                            const float* __restrict__ cosT,
                            const float* __restrict__ sinT,
                            int rowsize, int npairs) {
    int p = blockIdx.x * blockDim.x + threadIdx.x;
    if (p >= npairs) return;
    const int hp = rowsize >> 1;
    const int row = p / hp;
    const int pc = p - row * hp;
    const int s = row & (SS - 1);
    const int i = pc & 63;
    const float c = cosT[s * 64 + i];
    const float sn = sinT[s * 64 + i];
    float* base = tns + (size_t)row * rowsize + 2 * pc;
    const float x0 = base[0], x1 = base[1];
    base[0] = x0 * c - x1 * sn;
    base[1] = x0 * sn + x1 * c;
}

// ---------------------------------------------------------------------------
// Causal MQA flash attention, fp32, 2 query rows per thread.
// Interleaved dim ownership (sub + 4*tt) = conflict-free scalar LDS, and each
// Ks/Vs shared load now feeds TWO fma (one per q-row) -> halves LDS per FMA.
// Block covers 64 q-rows; thread (row, sub) owns rows qi0=qb*64+row and
// qi0+32. grid (SS/64, H, B), 128 threads.
// ---------------------------------------------------------------------------
__global__ void __launch_bounds__(128) flash_kernel2(const float* __restrict__ q,
                                                     const float* __restrict__ k,
                                                     const float* __restrict__ v,
                                                     float* __restrict__ out) {
    const int qb  = blockIdx.x;
    const int h   = blockIdx.y;
    const int b   = blockIdx.z;
    const int row = threadIdx.x >> 2;   // 0..31
    const int sub = threadIdx.x & 3;
    const int qi0 = qb * 64 + row;
    const int qi1 = qi0 + 32;

    __shared__ float Ks[32][HD];
    __shared__ float Vs[32][HD];

    float qf0[32], qf1[32], o0[32], o1[32];
    {
        const float* qrow0 = q + ((size_t)b * SS + qi0) * DD + h * HD;
        const float* qrow1 = q + ((size_t)b * SS + qi1) * DD + h * HD;
#pragma unroll
        for (int tt = 0; tt < 32; ++tt) {
            qf0[tt] = qrow0[sub + 4 * tt];
            qf1[tt] = qrow1[sub + 4 * tt];
            o0[tt] = 0.f;
            o1[tt] = 0.f;
        }
    }

    float m0v = -1e30f, l0 = 0.f, m1v = -1e30f, l1 = 0.f;
    const float scale = 0.08838834764831845f;  // 1/sqrt(128)

    const int kend = qb * 64 + 64;  // exclusive
    for (int k0 = 0; k0 < kend; k0 += 32) {
        {
            const float4* kg = (const float4*)(k + ((size_t)b * SS + k0) * HD);
            const float4* vg = (const float4*)(v + ((size_t)b * SS + k0) * HD);
            float4* ks4 = (float4*)&Ks[0][0];
            float4* vs4 = (float4*)&Vs[0][0];
#pragma unroll
            for (int it = 0; it < 8; ++it) {
                int idx = threadIdx.x + it * 128;
                ks4[idx] = kg[idx];
                vs4[idx] = vg[idx];
            }
        }
        __syncthreads();

        float s0[32], s1[32];
#pragma unroll
        for (int kk = 0; kk < 32; ++kk) {
            float a0 = 0.f, a1 = 0.f;
#pragma unroll
            for (int tt = 0; tt < 32; ++tt) {
                const float kv = Ks[kk][sub + 4 * tt];
                a0 += qf0[tt] * kv;
                a1 += qf1[tt] * kv;
            }
            s0[kk] = a0;
            s1[kk] = a1;
        }
#pragma unroll
        for (int kk = 0; kk < 32; ++kk) {
            float t0 = s0[kk];
            t0 += __shfl_xor_sync(0xffffffffu, t0, 1);
            t0 += __shfl_xor_sync(0xffffffffu, t0, 2);
            t0 *= scale;
            if (k0 + kk > qi0) t0 = -1e30f;
            s0[kk] = t0;
            float t1 = s1[kk];
            t1 += __shfl_xor_sync(0xffffffffu, t1, 1);
            t1 += __shfl_xor_sync(0xffffffffu, t1, 2);
            t1 *= scale;
            if (k0 + kk > qi1) t1 = -1e30f;
            s1[kk] = t1;
        }
        float tm0 = -1e30f, tm1 = -1e30f;
#pragma unroll
        for (int kk = 0; kk < 32; ++kk) {
            tm0 = fmaxf(tm0, s0[kk]);
            tm1 = fmaxf(tm1, s1[kk]);
        }
        const float mn0 = fmaxf(m0v, tm0);
        const float mn1 = fmaxf(m1v, tm1);
        const float c0 = __expf(m0v - mn0);
        const float c1 = __expf(m1v - mn1);
        float la0 = 0.f, la1 = 0.f;
#pragma unroll
        for (int kk = 0; kk < 32; ++kk) {
            s0[kk] = __expf(s0[kk] - mn0);
            la0 += s0[kk];
            s1[kk] = __expf(s1[kk] - mn1);
            la1 += s1[kk];
        }
        l0 = l0 * c0 + la0;
        l1 = l1 * c1 + la1;
        m0v = mn0;
        m1v = mn1;
#pragma unroll
        for (int tt = 0; tt < 32; ++tt) {
            o0[tt] *= c0;
            o1[tt] *= c1;
        }
#pragma unroll
        for (int kk = 0; kk < 32; ++kk) {
            const float p0 = s0[kk];
            const float p1 = s1[kk];
#pragma unroll
            for (int tt = 0; tt < 32; ++tt) {
                const float vv = Vs[kk][sub + 4 * tt];
                o0[tt] += p0 * vv;
                o1[tt] += p1 * vv;
            }
        }
        __syncthreads();
    }

    const float inv0 = 1.f / l0;
    const float inv1 = 1.f / l1;
    float* orow0 = out + ((size_t)b * SS + qi0) * DD + h * HD;
    float* orow1 = out + ((size_t)b * SS + qi1) * DD + h * HD;
#pragma unroll
    for (int tt = 0; tt < 32; ++tt) {
        orow0[sub + 4 * tt] = o0[tt] * inv0;
        orow1[sub + 4 * tt] = o1[tt] * inv1;
    }
}

// ---------------------------------------------------------------------------
extern "C" void kernel_launch(void* const* d_in, const int* in_sizes, int n_in,
                              void* d_out, int out_size) {
    const float* x    = (const float*)d_in[0];
    const float* Wq   = (const float*)d_in[1];
    const float* Wk   = (const float*)d_in[2];
    const float* Wv   = (const float*)d_in[3];
    const float* Wo   = (const float*)d_in[4];
    const float* rcos = (const float*)d_in[5];
    const float* rsin = (const float*)d_in[6];
    float* out = (float*)d_out;

    float *q_p, *k_p, *v_p, *att_p;
    cudaGetSymbolAddress((void**)&q_p, g_q);
    cudaGetSymbolAddress((void**)&k_p, g_k);
    cudaGetSymbolAddress((void**)&v_p, g_v);
    cudaGetSymbolAddress((void**)&att_p, g_att);

    __nv_bfloat16 *xhi, *xlo, *wqhi, *wqlo, *wkhi, *wklo, *wvhi, *wvlo, *wohi, *wolo, *ahi, *alo;
    cudaGetSymbolAddress((void**)&xhi, g_xhi);   cudaGetSymbolAddress((void**)&xlo, g_xlo);
    cudaGetSymbolAddress((void**)&wqhi, g_wqhi); cudaGetSymbolAddress((void**)&wqlo, g_wqlo);
    cudaGetSymbolAddress((void**)&wkhi, g_wkhi); cudaGetSymbolAddress((void**)&wklo, g_wklo);
    cudaGetSymbolAddress((void**)&wvhi, g_wvhi); cudaGetSymbolAddress((void**)&wvlo, g_wvlo);
    cudaGetSymbolAddress((void**)&wohi, g_wohi); cudaGetSymbolAddress((void**)&wolo, g_wolo);
    cudaGetSymbolAddress((void**)&ahi, g_ahi);   cudaGetSymbolAddress((void**)&alo, g_alo);

    cudaFuncSetAttribute(gemm_bf16pair, cudaFuncAttributeMaxDynamicSharedMemorySize, GEMM_DYN_SMEM);

    const int M = MM;  // 4096

    // splits
    split_kernel<<<(M * DD + 255) / 256, 256>>>(x, xhi, xlo, M * DD);
    split_kernel<<<(DD * DD + 255) / 256, 256>>>(Wq, wqhi, wqlo, DD * DD);
    split_kernel<<<(HD * DD + 255) / 256, 256>>>(Wk, wkhi, wklo, HD * DD);
    split_kernel<<<(HD * DD + 255) / 256, 256>>>(Wv, wvhi, wvlo, HD * DD);
    split_kernel<<<(DD * DD + 255) / 256, 256>>>(Wo, wohi, wolo, DD * DD);

    // projections on tensor cores (mma.sync)
    gemm_bf16pair<<<dim3(DD / 128, M / 128), 256, GEMM_DYN_SMEM>>>(xhi, xlo, wqhi, wqlo, q_p, DD, DD);
    gemm_bf16pair<<<dim3(HD / 128, M / 128), 256, GEMM_DYN_SMEM>>>(xhi, xlo, wkhi, wklo, k_p, HD, DD);
    gemm_bf16pair<<<dim3(HD / 128, M / 128), 256, GEMM_DYN_SMEM>>>(xhi, xlo, wvhi, wvlo, v_p, HD, DD);

    // RoPE
    {
        int npq = M * DD / 2;
        rope_kernel<<<(npq + 255) / 256, 256>>>(q_p, rcos, rsin, DD, npq);
        int npk = M * HD / 2;
        rope_kernel<<<(npk + 255) / 256, 256>>>(k_p, rcos, rsin, HD, npk);
    }

    // attention (2 q-rows per thread)
    flash_kernel2<<<dim3(SS / 64, HH, BB), 128>>>(q_p, k_p, v_p, att_p);

    // output projection
    split_kernel<<<(M * DD + 255) / 256, 256>>>(att_p, ahi, alo, M * DD);
    gemm_bf16pair<<<dim3(DD / 128, M / 128), 256, GEMM_DYN_SMEM>>>(ahi, alo, wohi, wolo, out, DD, DD);
}

// round 16
// speedup vs baseline: 3.5431x; 1.3297x over previous
#include <cuda_runtime.h>
#include <cuda_bf16.h>
#include <math.h>
#include <stdint.h>

#define BB 2
#define SS 2048
#define DD 2048
#define HH 16
#define HD 128
#define MM (BB*SS)   // 4096

// ---------------- scratch (device globals; no allocation allowed) ----------
__device__ float g_q[MM * DD];
__device__ float g_k[MM * HD];
__device__ float g_v[MM * HD];
__device__ float g_att[MM * DD];

__device__ __nv_bfloat16 g_xhi[MM * DD], g_xlo[MM * DD];
__device__ __nv_bfloat16 g_wqhi[DD * DD], g_wqlo[DD * DD];
__device__ __nv_bfloat16 g_wkhi[HD * DD], g_wklo[HD * DD];
__device__ __nv_bfloat16 g_wvhi[HD * DD], g_wvlo[HD * DD];
__device__ __nv_bfloat16 g_wohi[DD * DD], g_wolo[DD * DD];
__device__ __nv_bfloat16 g_ahi[MM * DD], g_alo[MM * DD];

// ---------------- helpers ---------------------------------------------------
__device__ __forceinline__ uint32_t smem_u32(const void* p) {
    uint32_t a;
    asm("{ .reg .u64 t; cvta.to.shared.u64 t, %1; cvt.u32.u64 %0, t; }" : "=r"(a) : "l"(p));
    return a;
}

__device__ __forceinline__ void ldmatrix_x4(uint32_t* r, uint32_t addr) {
    asm volatile("ldmatrix.sync.aligned.m8n8.x4.shared.b16 {%0,%1,%2,%3}, [%4];"
                 : "=r"(r[0]), "=r"(r[1]), "=r"(r[2]), "=r"(r[3]) : "r"(addr));
}

__device__ __forceinline__ void mma_bf16(float* c, const uint32_t* a, uint32_t b0, uint32_t b1) {
    asm volatile(
        "mma.sync.aligned.m16n8k16.row.col.f32.bf16.bf16.f32 "
        "{%0,%1,%2,%3}, {%4,%5,%6,%7}, {%8,%9}, {%0,%1,%2,%3};"
        : "+f"(c[0]), "+f"(c[1]), "+f"(c[2]), "+f"(c[3])
        : "r"(a[0]), "r"(a[1]), "r"(a[2]), "r"(a[3]), "r"(b0), "r"(b1));
}

// ---------------------------------------------------------------------------
// Split fp32 -> bf16 (hi, lo)
// ---------------------------------------------------------------------------
__global__ void split_kernel(const float* __restrict__ src,
                             __nv_bfloat16* __restrict__ hi,
                             __nv_bfloat16* __restrict__ lo, int n) {
    int i = blockIdx.x * blockDim.x + threadIdx.x;
    if (i >= n) return;
    float x = src[i];
    __nv_bfloat16 h = __float2bfloat16(x);
    hi[i] = h;
    lo[i] = __float2bfloat16(x - __bfloat162float(h));
}

// ---------------------------------------------------------------------------
// mma.sync GEMM (unchanged from measured 3619/3477us configs).
// ---------------------------------------------------------------------------
#define STAGE_BYTES 32768          // A tile 16KB + W tile 16KB
#define GEMM_DYN_SMEM (2 * STAGE_BYTES + 1024)

__device__ __forceinline__ void load_stage(const __nv_bfloat16* __restrict__ Ahi,
                                           const __nv_bfloat16* __restrict__ Alo,
                                           const __nv_bfloat16* __restrict__ Whi,
                                           const __nv_bfloat16* __restrict__ Wlo,
                                           int m0, int n0, int Kdim, int k0, uint32_t sb) {
#pragma unroll
    for (int it = 0; it < 8; ++it) {
        int id = threadIdx.x + it * 256;          // 0..2047
        int tile = id >> 10;                       // 0 = A, 1 = W
        int off = (id & 1023) * 16;                // byte offset inside 16KB tile
        int row = off >> 7;                        // 128B rows
        int chunk = (off >> 4) & 7;                // 16B chunk in row
        int grow = (tile ? n0 : m0) + row;
        int kcol = k0 + (chunk & 3) * 8;
        const __nv_bfloat16* src;
        if (tile == 0) src = (chunk < 4 ? Ahi : Alo) + (size_t)grow * Kdim + kcol;
        else           src = (chunk < 4 ? Whi : Wlo) + (size_t)grow * Kdim + kcol;
        uint32_t sa = sb + (uint32_t)tile * 16384u + ((uint32_t)off ^ (((uint32_t)off >> 3) & 0x70));
        uint64_t ga = (uint64_t)__cvta_generic_to_global((const void*)src);
        asm volatile("cp.async.cg.shared.global [%0], [%1], 16;" :: "r"(sa), "l"(ga) : "memory");
    }
}

__global__ void __launch_bounds__(256, 1)
gemm_bf16pair(const __nv_bfloat16* __restrict__ Ahi, const __nv_bfloat16* __restrict__ Alo,
              const __nv_bfloat16* __restrict__ Whi, const __nv_bfloat16* __restrict__ Wlo,
              float* __restrict__ C, int Ncols, int Kdim) {
    extern __shared__ char dsm[];
    const uint32_t sbase = (smem_u32(dsm) + 1023u) & ~1023u;

    const int tid = threadIdx.x;
    const int wid = tid >> 5;
    const int lane = tid & 31;
    const int warp_m = wid >> 2;     // 0..1
    const int warp_n = wid & 3;      // 0..3
    const int m0 = blockIdx.y * 128;
    const int n0 = blockIdx.x * 128;

    float acc[4][4][4];
#pragma unroll
    for (int i = 0; i < 4; ++i)
#pragma unroll
        for (int j = 0; j < 4; ++j)
#pragma unroll
            for (int r = 0; r < 4; ++r) acc[i][j][r] = 0.f;

    const int a_row_l = (lane & 15);
    const int a_chk_l = (lane >> 4);           // 0..1
    const int b_row_l = ((lane >> 4) & 1) * 8 + (lane & 7);
    const int b_chk_l = ((lane >> 3) & 1);

    const int NC = Kdim >> 5;   // BK = 32

    load_stage(Ahi, Alo, Whi, Wlo, m0, n0, Kdim, 0, sbase);
    asm volatile("cp.async.commit_group;" ::: "memory");

    for (int c = 0; c < NC; ++c) {
        if (c + 1 < NC) {
            load_stage(Ahi, Alo, Whi, Wlo, m0, n0, Kdim, (c + 1) << 5,
                       sbase + (uint32_t)((c + 1) & 1) * STAGE_BYTES);
            asm volatile("cp.async.commit_group;" ::: "memory");
            asm volatile("cp.async.wait_group 1;" ::: "memory");
        } else {
            asm volatile("cp.async.wait_group 0;" ::: "memory");
        }
        __syncthreads();

        const uint32_t Asw = sbase + (uint32_t)(c & 1) * STAGE_BYTES;
        const uint32_t Wsw = Asw + 16384u;

#pragma unroll
        for (int ks = 0; ks < 2; ++ks) {
            uint32_t afr[2][4][4];
#pragma unroll
            for (int p = 0; p < 2; ++p)
#pragma unroll
                for (int tm = 0; tm < 4; ++tm) {
                    int row = warp_m * 64 + tm * 16 + a_row_l;
                    int chunk = p * 4 + 2 * ks + a_chk_l;
                    uint32_t byte = (uint32_t)(row * 128 + chunk * 16);
                    byte ^= ((byte >> 3) & 0x70);
                    ldmatrix_x4(afr[p][tm], Asw + byte);
                }
            uint32_t bfr[2][2][4];
#pragma unroll
            for (int p = 0; p < 2; ++p)
#pragma unroll
                for (int nb = 0; nb < 2; ++nb) {
                    int row = warp_n * 32 + nb * 16 + b_row_l;
                    int chunk = p * 4 + 2 * ks + b_chk_l;
                    uint32_t byte = (uint32_t)(row * 128 + chunk * 16);
                    byte ^= ((byte >> 3) & 0x70);
                    ldmatrix_x4(bfr[p][nb], Wsw + byte);
                }
            // Pass 1: hi*hi
#pragma unroll
            for (int tm = 0; tm < 4; ++tm)
#pragma unroll
                for (int nt = 0; nt < 4; ++nt) {
                    const int nb = nt >> 1, half = (nt & 1) * 2;
                    mma_bf16(acc[tm][nt], afr[0][tm], bfr[0][nb][half], bfr[0][nb][half + 1]);
                }
            // Pass 2: hi*lo
#pragma unroll
            for (int tm = 0; tm < 4; ++tm)
#pragma unroll
                for (int nt = 0; nt < 4; ++nt) {
                    const int nb = nt >> 1, half = (nt & 1) * 2;
                    mma_bf16(acc[tm][nt], afr[0][tm], bfr[1][nb][half], bfr[1][nb][half + 1]);
                }
            // Pass 3: lo*hi
#pragma unroll
            for (int tm = 0; tm < 4; ++tm)
#pragma unroll
                for (int nt = 0; nt < 4; ++nt) {
                    const int nb = nt >> 1, half = (nt & 1) * 2;
                    mma_bf16(acc[tm][nt], afr[1][tm], bfr[0][nb][half], bfr[0][nb][half + 1]);
                }
        }
        __syncthreads();
    }

    // epilogue
    const int g = lane >> 2, tig = lane & 3;
#pragma unroll
    for (int tm = 0; tm < 4; ++tm) {
#pragma unroll
        for (int nt = 0; nt < 4; ++nt) {
            int gr = m0 + warp_m * 64 + tm * 16 + g;
            int gc = n0 + warp_n * 32 + nt * 8 + tig * 2;
            *(float2*)&C[(size_t)gr * Ncols + gc] = make_float2(acc[tm][nt][0], acc[tm][nt][1]);
            *(float2*)&C[(size_t)(gr + 8) * Ncols + gc] = make_float2(acc[tm][nt][2], acc[tm][nt][3]);
        }
    }
}

// ---------------------------------------------------------------------------
// In-place RoPE
// ---------------------------------------------------------------------------
__global__ void rope_kernel(float* __restrict__ tns,
                            const float* __restrict__ cosT,
                            const float* __restrict__ sinT,
                            int rowsize, int npairs) {
    int p = blockIdx.x * blockDim.x + threadIdx.x;
    if (p >= npairs) return;
    const int hp = rowsize >> 1;
    const int row = p / hp;
    const int pc = p - row * hp;
    const int s = row & (SS - 1);
    const int i = pc & 63;
    const float c = cosT[s * 64 + i];
    const float sn = sinT[s * 64 + i];
    float* base = tns + (size_t)row * rowsize + 2 * pc;
    const float x0 = base[0], x1 = base[1];
    base[0] = x0 * c - x1 * sn;
    base[1] = x0 * sn + x1 * c;
}

// ---------------------------------------------------------------------------
// Causal MQA flash attention, fp32: 2 q-rows per thread, 8 threads per
// row-pair (16 dims each, interleaved sub+8*t -> conflict-free broadcast LDS,
// each shared value feeds 2 FMAs). 256 threads cover 64 q-rows.
// Registers: qf0/1[16] + o0/1[16] + s0/1[32] = 128 -> no spills.
// grid (SS/64, H, B).
// ---------------------------------------------------------------------------
__global__ void __launch_bounds__(256) flash_kernel3(const float* __restrict__ q,
                                                     const float* __restrict__ k,
                                                     const float* __restrict__ v,
                                                     float* __restrict__ out) {
    const int qb  = blockIdx.x;
    const int h   = blockIdx.y;
    const int b   = blockIdx.z;
    const int rp  = threadIdx.x >> 3;   // 0..31 row-pair id
    const int sub = threadIdx.x & 7;    // 0..7 dim group
    const int qi0 = qb * 64 + rp;
    const int qi1 = qi0 + 32;

    __shared__ float Ks[32][HD];
    __shared__ float Vs[32][HD];

    float qf0[16], qf1[16], o0[16], o1[16];
    {
        const float* qrow0 = q + ((size_t)b * SS + qi0) * DD + h * HD;
        const float* qrow1 = q + ((size_t)b * SS + qi1) * DD + h * HD;
#pragma unroll
        for (int t = 0; t < 16; ++t) {
            qf0[t] = qrow0[sub + 8 * t];
            qf1[t] = qrow1[sub + 8 * t];
            o0[t] = 0.f;
            o1[t] = 0.f;
        }
    }

    float m0v = -1e30f, l0 = 0.f, m1v = -1e30f, l1 = 0.f;
    const float scale = 0.08838834764831845f;  // 1/sqrt(128)

    const int kend = qb * 64 + 64;  // exclusive
    for (int k0 = 0; k0 < kend; k0 += 32) {
        {
            const float4* kg = (const float4*)(k + ((size_t)b * SS + k0) * HD);
            const float4* vg = (const float4*)(v + ((size_t)b * SS + k0) * HD);
            float4* ks4 = (float4*)&Ks[0][0];
            float4* vs4 = (float4*)&Vs[0][0];
#pragma unroll
            for (int it = 0; it < 4; ++it) {
                int idx = threadIdx.x + it * 256;
                ks4[idx] = kg[idx];
                vs4[idx] = vg[idx];
            }
        }
        __syncthreads();

        float s0[32], s1[32];
#pragma unroll
        for (int kk = 0; kk < 32; ++kk) {
            float a0 = 0.f, a1 = 0.f;
#pragma unroll
            for (int t = 0; t < 16; ++t) {
                const float kv = Ks[kk][sub + 8 * t];
                a0 += qf0[t] * kv;
                a1 += qf1[t] * kv;
            }
            s0[kk] = a0;
            s1[kk] = a1;
        }
#pragma unroll
        for (int kk = 0; kk < 32; ++kk) {
            float t0 = s0[kk];
            t0 += __shfl_xor_sync(0xffffffffu, t0, 1);
            t0 += __shfl_xor_sync(0xffffffffu, t0, 2);
            t0 += __shfl_xor_sync(0xffffffffu, t0, 4);
            t0 *= scale;
            if (k0 + kk > qi0) t0 = -1e30f;
            s0[kk] = t0;
            float t1 = s1[kk];
            t1 += __shfl_xor_sync(0xffffffffu, t1, 1);
            t1 += __shfl_xor_sync(0xffffffffu, t1, 2);
            t1 += __shfl_xor_sync(0xffffffffu, t1, 4);
            t1 *= scale;
            if (k0 + kk > qi1) t1 = -1e30f;
            s1[kk] = t1;
        }
        float tm0 = -1e30f, tm1 = -1e30f;
#pragma unroll
        for (int kk = 0; kk < 32; ++kk) {
            tm0 = fmaxf(tm0, s0[kk]);
            tm1 = fmaxf(tm1, s1[kk]);
        }
        const float mn0 = fmaxf(m0v, tm0);
        const float mn1 = fmaxf(m1v, tm1);
        const float c0 = __expf(m0v - mn0);
        const float c1 = __expf(m1v - mn1);
        float la0 = 0.f, la1 = 0.f;
#pragma unroll
        for (int kk = 0; kk < 32; ++kk) {
            s0[kk] = __expf(s0[kk] - mn0);
            la0 += s0[kk];
            s1[kk] = __expf(s1[kk] - mn1);
            la1 += s1[kk];
        }
        l0 = l0 * c0 + la0;
        l1 = l1 * c1 + la1;
        m0v = mn0;
        m1v = mn1;
#pragma unroll
        for (int t = 0; t < 16; ++t) {
            o0[t] *= c0;
            o1[t] *= c1;
        }
#pragma unroll
        for (int kk = 0; kk < 32; ++kk) {
            const float p0 = s0[kk];
            const float p1 = s1[kk];
#pragma unroll
            for (int t = 0; t < 16; ++t) {
                const float vv = Vs[kk][sub + 8 * t];
                o0[t] += p0 * vv;
                o1[t] += p1 * vv;
            }
        }
        __syncthreads();
    }

    const float inv0 = 1.f / l0;
    const float inv1 = 1.f / l1;
    float* orow0 = out + ((size_t)b * SS + qi0) * DD + h * HD;
    float* orow1 = out + ((size_t)b * SS + qi1) * DD + h * HD;
#pragma unroll
    for (int t = 0; t < 16; ++t) {
        orow0[sub + 8 * t] = o0[t] * inv0;
        orow1[sub + 8 * t] = o1[t] * inv1;
    }
}

// ---------------------------------------------------------------------------
extern "C" void kernel_launch(void* const* d_in, const int* in_sizes, int n_in,
                              void* d_out, int out_size) {
    const float* x    = (const float*)d_in[0];
    const float* Wq   = (const float*)d_in[1];
    const float* Wk   = (const float*)d_in[2];
    const float* Wv   = (const float*)d_in[3];
    const float* Wo   = (const float*)d_in[4];
    const float* rcos = (const float*)d_in[5];
    const float* rsin = (const float*)d_in[6];
    float* out = (float*)d_out;

    float *q_p, *k_p, *v_p, *att_p;
    cudaGetSymbolAddress((void**)&q_p, g_q);
    cudaGetSymbolAddress((void**)&k_p, g_k);
    cudaGetSymbolAddress((void**)&v_p, g_v);
    cudaGetSymbolAddress((void**)&att_p, g_att);

    __nv_bfloat16 *xhi, *xlo, *wqhi, *wqlo, *wkhi, *wklo, *wvhi, *wvlo, *wohi, *wolo, *ahi, *alo;
    cudaGetSymbolAddress((void**)&xhi, g_xhi);   cudaGetSymbolAddress((void**)&xlo, g_xlo);
    cudaGetSymbolAddress((void**)&wqhi, g_wqhi); cudaGetSymbolAddress((void**)&wqlo, g_wqlo);
    cudaGetSymbolAddress((void**)&wkhi, g_wkhi); cudaGetSymbolAddress((void**)&wklo, g_wklo);
    cudaGetSymbolAddress((void**)&wvhi, g_wvhi); cudaGetSymbolAddress((void**)&wvlo, g_wvlo);
    cudaGetSymbolAddress((void**)&wohi, g_wohi); cudaGetSymbolAddress((void**)&wolo, g_wolo);
    cudaGetSymbolAddress((void**)&ahi, g_ahi);   cudaGetSymbolAddress((void**)&alo, g_alo);

    cudaFuncSetAttribute(gemm_bf16pair, cudaFuncAttributeMaxDynamicSharedMemorySize, GEMM_DYN_SMEM);

    const int M = MM;  // 4096

    // splits
    split_kernel<<<(M * DD + 255) / 256, 256>>>(x, xhi, xlo, M * DD);
    split_kernel<<<(DD * DD + 255) / 256, 256>>>(Wq, wqhi, wqlo, DD * DD);
    split_kernel<<<(HD * DD + 255) / 256, 256>>>(Wk, wkhi, wklo, HD * DD);
    split_kernel<<<(HD * DD + 255) / 256, 256>>>(Wv, wvhi, wvlo, HD * DD);
    split_kernel<<<(DD * DD + 255) / 256, 256>>>(Wo, wohi, wolo, DD * DD);

    // projections on tensor cores (mma.sync)
    gemm_bf16pair<<<dim3(DD / 128, M / 128), 256, GEMM_DYN_SMEM>>>(xhi, xlo, wqhi, wqlo, q_p, DD, DD);
    gemm_bf16pair<<<dim3(HD / 128, M / 128), 256, GEMM_DYN_SMEM>>>(xhi, xlo, wkhi, wklo, k_p, HD, DD);
    gemm_bf16pair<<<dim3(HD / 128, M / 128), 256, GEMM_DYN_SMEM>>>(xhi, xlo, wvhi, wvlo, v_p, HD, DD);

    // RoPE
    {
        int npq = M * DD / 2;
        rope_kernel<<<(npq + 255) / 256, 256>>>(q_p, rcos, rsin, DD, npq);
        int npk = M * HD / 2;
        rope_kernel<<<(npk + 255) / 256, 256>>>(k_p, rcos, rsin, HD, npk);
    }

    // attention (2 q-rows per thread, 8 threads/row-pair)
    flash_kernel3<<<dim3(SS / 64, HH, BB), 256>>>(q_p, k_p, v_p, att_p);

    // output projection
    split_kernel<<<(M * DD + 255) / 256, 256>>>(att_p, ahi, alo, M * DD);
    gemm_bf16pair<<<dim3(DD / 128, M / 128), 256, GEMM_DYN_SMEM>>>(ahi, alo, wohi, wolo, out, DD, DD);
}